// round 1
// baseline (speedup 1.0000x reference)
#include <cuda_runtime.h>

// Problem constants
#define BB   1024
#define TT   512
#define IN   6
#define HH   64
#define GG   256    // 4*H gates
#define RR   8      // batch rows per CTA
#define NTH  256
#define NCTA (BB / RR)   // 128

// Shared memory layout (in floats)
#define OFF_WHH0  0                      // [64][256]
#define OFF_WIH1  (OFF_WHH0 + HH*GG)     // [64][256]
#define OFF_WHH1  (OFF_WIH1 + HH*GG)     // [64][256]
#define OFF_WIH0  (OFF_WHH1 + HH*GG)     // [6][256]
#define OFF_B0    (OFF_WIH0 + IN*GG)     // [256]
#define OFF_B1    (OFF_B0 + GG)          // [256]
#define OFF_GSH   (OFF_B1 + GG)          // [8][256]
#define OFF_HT0   (OFF_GSH + RR*GG)      // [64][8] transposed h (k-major)
#define OFF_HT1   (OFF_HT0 + HH*RR)      // [64][8]
#define OFF_XT    (OFF_HT1 + HH*RR)      // [6][8] (pad to 64)
#define SMEM_FLOATS (OFF_XT + 64)
#define SMEM_BYTES  (SMEM_FLOATS * 4)

__device__ __forceinline__ float fex2(float x) {
    float y; asm("ex2.approx.ftz.f32 %0, %1;" : "=f"(y) : "f"(x)); return y;
}
__device__ __forceinline__ float frcp(float x) {
    float y; asm("rcp.approx.ftz.f32 %0, %1;" : "=f"(y) : "f"(x)); return y;
}
__device__ __forceinline__ float sigmoidf_(float x) {
    // 1 / (1 + 2^(-x*log2(e)))
    return frcp(1.0f + fex2(-1.4426950408889634f * x));
}
__device__ __forceinline__ float tanhf_(float x) {
    // 2*sigmoid(2x) - 1
    return fmaf(2.0f, frcp(1.0f + fex2(-2.8853900817779268f * x)), -1.0f);
}

// Accumulate acc[0..7] += W[k][g] * hT[k][r] over K columns.
// W layout: [K][256] (gate-contiguous -> conflict-free per-warp loads).
// hT layout: [K][8] (row-contiguous -> 2x float4 broadcast per k).
__device__ __forceinline__ void matvec_acc(const float* __restrict__ Ws,
                                           const float* __restrict__ hT,
                                           int g, int K, float acc[RR]) {
#pragma unroll 4
    for (int k = 0; k < K; k++) {
        float w = Ws[k * GG + g];
        float4 ha = *(const float4*)(hT + k * RR);
        float4 hb = *(const float4*)(hT + k * RR + 4);
        acc[0] = fmaf(ha.x, w, acc[0]);
        acc[1] = fmaf(ha.y, w, acc[1]);
        acc[2] = fmaf(ha.z, w, acc[2]);
        acc[3] = fmaf(ha.w, w, acc[3]);
        acc[4] = fmaf(hb.x, w, acc[4]);
        acc[5] = fmaf(hb.y, w, acc[5]);
        acc[6] = fmaf(hb.z, w, acc[6]);
        acc[7] = fmaf(hb.w, w, acc[7]);
    }
}

// One (row r, hidden j) LSTM cell update from the gate buffer.
__device__ __forceinline__ void lstm_update(const float* __restrict__ gsh,
                                            float* __restrict__ hT,
                                            float& c, int r, int j) {
    float gi = sigmoidf_(gsh[r * GG + j]);
    float gf = sigmoidf_(gsh[r * GG + HH + j]);
    float gg = tanhf_  (gsh[r * GG + 2 * HH + j]);
    float go = sigmoidf_(gsh[r * GG + 3 * HH + j]);
    c = fmaf(gf, c, gi * gg);
    hT[j * RR + r] = go * tanhf_(c);
}

__global__ void __launch_bounds__(NTH, 1)
lstm_net_kernel(const float* __restrict__ x,
                const float* __restrict__ Wih0, const float* __restrict__ Whh0,
                const float* __restrict__ bih0, const float* __restrict__ bhh0,
                const float* __restrict__ Wih1, const float* __restrict__ Whh1,
                const float* __restrict__ bih1, const float* __restrict__ bhh1,
                const float* __restrict__ Wfc1, const float* __restrict__ bfc1,
                const float* __restrict__ Wfc2, const float* __restrict__ bfc2,
                float* __restrict__ out) {
    extern __shared__ float s[];
    float* Whh0s = s + OFF_WHH0;
    float* Wih1s = s + OFF_WIH1;
    float* Whh1s = s + OFF_WHH1;
    float* Wih0s = s + OFF_WIH0;
    float* b0s   = s + OFF_B0;
    float* b1s   = s + OFF_B1;
    float* gsh   = s + OFF_GSH;
    float* hT0   = s + OFF_HT0;
    float* hT1   = s + OFF_HT1;
    float* xT    = s + OFF_XT;

    const int tid = threadIdx.x;
    const int b0  = blockIdx.x * RR;

    // ---- Load weights to shared (transposed: [k][g]) ----
    for (int i = tid; i < HH * GG; i += NTH) {
        int g = i >> 6;        // /64
        int k = i & 63;
        float w0 = Whh0[i];    // coalesced global reads
        float w1 = Wih1[i];
        float w2 = Whh1[i];
        Whh0s[k * GG + g] = w0;
        Wih1s[k * GG + g] = w1;
        Whh1s[k * GG + g] = w2;
    }
    for (int i = tid; i < IN * GG; i += NTH) {
        int g = i / IN;
        int k = i - g * IN;
        Wih0s[k * GG + g] = Wih0[i];
    }
    if (tid < GG) {
        b0s[tid] = bih0[tid] + bhh0[tid];
        b1s[tid] = bih1[tid] + bhh1[tid];
    }
    for (int i = tid; i < HH * RR; i += NTH) { hT0[i] = 0.0f; hT1[i] = 0.0f; }

    // x prefetch: threads 0..47 each own (k, r)
    const int xk = tid >> 3;       // 0..5 (for tid<48)
    const int xr = tid & 7;
    float xreg = 0.0f;
    if (tid < IN * RR)
        xreg = x[(size_t)(b0 + xr) * TT * IN + xk];

    // cell state registers: this thread owns (ur, uj) and (ur+4, uj) per layer
    const int ur = tid >> 6;       // 0..3
    const int uj = tid & 63;
    float c0a = 0.0f, c0b = 0.0f, c1a = 0.0f, c1b = 0.0f;

    __syncthreads();

    for (int t = 0; t < TT; t++) {
        // publish x_t, then prefetch x_{t+1}
        if (tid < IN * RR) xT[xk * RR + xr] = xreg;
        __syncthreads();
        if (tid < IN * RR && t + 1 < TT)
            xreg = x[(size_t)(b0 + xr) * TT * IN + (size_t)(t + 1) * IN + xk];

        // ---- Layer 0 gates: thread g = tid computes gate g for 8 rows ----
        float acc[RR];
        {
            float b = b0s[tid];
#pragma unroll
            for (int r = 0; r < RR; r++) acc[r] = b;
        }
#pragma unroll
        for (int k = 0; k < IN; k++) {
            float w = Wih0s[k * GG + tid];
            float4 xa = *(const float4*)(xT + k * RR);
            float4 xb = *(const float4*)(xT + k * RR + 4);
            acc[0] = fmaf(xa.x, w, acc[0]);
            acc[1] = fmaf(xa.y, w, acc[1]);
            acc[2] = fmaf(xa.z, w, acc[2]);
            acc[3] = fmaf(xa.w, w, acc[3]);
            acc[4] = fmaf(xb.x, w, acc[4]);
            acc[5] = fmaf(xb.y, w, acc[5]);
            acc[6] = fmaf(xb.z, w, acc[6]);
            acc[7] = fmaf(xb.w, w, acc[7]);
        }
        matvec_acc(Whh0s, hT0, tid, HH, acc);
#pragma unroll
        for (int r = 0; r < RR; r++) gsh[r * GG + tid] = acc[r];
        __syncthreads();

        // ---- Layer 0 cell update ----
        lstm_update(gsh, hT0, c0a, ur, uj);
        lstm_update(gsh, hT0, c0b, ur + 4, uj);
        __syncthreads();

        // ---- Layer 1 gates ----
        {
            float b = b1s[tid];
#pragma unroll
            for (int r = 0; r < RR; r++) acc[r] = b;
        }
        matvec_acc(Wih1s, hT0, tid, HH, acc);
        matvec_acc(Whh1s, hT1, tid, HH, acc);
#pragma unroll
        for (int r = 0; r < RR; r++) gsh[r * GG + tid] = acc[r];
        __syncthreads();

        // ---- Layer 1 cell update ----
        lstm_update(gsh, hT1, c1a, ur, uj);
        lstm_update(gsh, hT1, c1b, ur + 4, uj);
        __syncthreads();
    }

    // ---- FC head on final h of layer 1 ----
    // warp w handles row r=w; lane m (0..31) handles FC_HID unit m
    {
        const int wrp = tid >> 5;    // 0..7 -> row
        const int m   = tid & 31;    // 0..31 -> fc1 unit
        float acc2 = bfc1[m];
#pragma unroll 8
        for (int k = 0; k < HH; k++)
            acc2 = fmaf(hT1[k * RR + wrp], Wfc1[m * HH + k], acc2);
        acc2 = fmaxf(acc2, 0.0f) * Wfc2[m];
#pragma unroll
        for (int off = 16; off > 0; off >>= 1)
            acc2 += __shfl_down_sync(0xffffffffu, acc2, off);
        if (m == 0)
            out[b0 + wrp] = acc2 + bfc2[0];
    }
}

extern "C" void kernel_launch(void* const* d_in, const int* in_sizes, int n_in,
                              void* d_out, int out_size) {
    const float* x    = (const float*)d_in[0];
    const float* Wih0 = (const float*)d_in[1];
    const float* Whh0 = (const float*)d_in[2];
    const float* bih0 = (const float*)d_in[3];
    const float* bhh0 = (const float*)d_in[4];
    const float* Wih1 = (const float*)d_in[5];
    const float* Whh1 = (const float*)d_in[6];
    const float* bih1 = (const float*)d_in[7];
    const float* bhh1 = (const float*)d_in[8];
    const float* Wfc1 = (const float*)d_in[9];
    const float* bfc1 = (const float*)d_in[10];
    const float* Wfc2 = (const float*)d_in[11];
    const float* bfc2 = (const float*)d_in[12];
    float* out = (float*)d_out;

    cudaFuncSetAttribute(lstm_net_kernel,
                         cudaFuncAttributeMaxDynamicSharedMemorySize, SMEM_BYTES);
    lstm_net_kernel<<<NCTA, NTH, SMEM_BYTES>>>(
        x, Wih0, Whh0, bih0, bhh0, Wih1, Whh1, bih1, bhh1,
        Wfc1, bfc1, Wfc2, bfc2, out);
}

// round 2
// speedup vs baseline: 1.1292x; 1.1292x over previous
#include <cuda_runtime.h>

// Problem constants
#define BB   1024
#define TT   512
#define IN   6
#define HH   64
#define GG   256    // 4*H gates = threads per CTA
#define RR   8      // batch rows per CTA
#define NTH  256
#define NCTA (BB / RR)   // 128

#define NKP   (HH / 2)   // 32 k-pairs for H=64
#define NKPX  (IN / 2)   // 3 k-pairs for input dim 6
#define HSTR  20         // floats per k-pair row in hT (16 data + 4 pad, 2-way STS conflicts)

// Shared memory layout (in floats). Weights stored as f32x2 pairs over k:
// W2[(kp*GG + g)*2 + parity] = W[g][2*kp + parity]
#define OFF_W2HH0 0                          // 32*256*2 = 16384
#define OFF_W2IH1 (OFF_W2HH0 + NKP*GG*2)     // 16384
#define OFF_W2HH1 (OFF_W2IH1 + NKP*GG*2)     // 16384
#define OFF_W2IH0 (OFF_W2HH1 + NKP*GG*2)     // 3*256*2 = 1536
#define OFF_B0    (OFF_W2IH0 + NKPX*GG*2)    // 256
#define OFF_B1    (OFF_B0 + GG)              // 256
#define OFF_GSH   (OFF_B1 + GG)              // 8*256 = 2048
#define OFF_HT0   (OFF_GSH + RR*GG)          // 32*20 = 640
#define OFF_HT1   (OFF_HT0 + NKP*HSTR)       // 640
#define OFF_XT    (OFF_HT1 + NKP*HSTR)       // 3*20 = 60 -> pad 64
#define SMEM_FLOATS (OFF_XT + 64)
#define SMEM_BYTES  (SMEM_FLOATS * 4)

typedef unsigned long long u64;

__device__ __forceinline__ u64 ffma2(u64 a, u64 b, u64 c) {
    u64 d;
    asm("fma.rn.f32x2 %0, %1, %2, %3;" : "=l"(d) : "l"(a), "l"(b), "l"(c));
    return d;
}
__device__ __forceinline__ float hsum2(u64 a) {
    union { u64 u; float2 f; } cvt; cvt.u = a;
    return cvt.f.x + cvt.f.y;
}

__device__ __forceinline__ float fex2(float x) {
    float y; asm("ex2.approx.ftz.f32 %0, %1;" : "=f"(y) : "f"(x)); return y;
}
__device__ __forceinline__ float frcp(float x) {
    float y; asm("rcp.approx.ftz.f32 %0, %1;" : "=f"(y) : "f"(x)); return y;
}
__device__ __forceinline__ float sigmoidf_(float x) {
    return frcp(1.0f + fex2(-1.4426950408889634f * x));
}
__device__ __forceinline__ float tanhf_(float x) {
    return fmaf(2.0f, frcp(1.0f + fex2(-2.8853900817779268f * x)), -1.0f);
}

// acc[r] (f32x2 over k-parity) += W2[kp][g] * h2[kp][r], kp in [0, NKPC)
template <int NKPC>
__device__ __forceinline__ void mv2(const float* __restrict__ W2s,
                                    const float* __restrict__ hT,
                                    int g, u64 acc[RR]) {
#pragma unroll 4
    for (int kp = 0; kp < NKPC; kp++) {
        u64 w2 = *(const u64*)(W2s + (kp * GG + g) * 2);         // LDS.64, conflict-free
        const ulonglong2* hp = (const ulonglong2*)(hT + kp * HSTR);
        ulonglong2 p0 = hp[0], p1 = hp[1], p2 = hp[2], p3 = hp[3]; // 4x LDS.128 broadcast
        acc[0] = ffma2(p0.x, w2, acc[0]);
        acc[1] = ffma2(p0.y, w2, acc[1]);
        acc[2] = ffma2(p1.x, w2, acc[2]);
        acc[3] = ffma2(p1.y, w2, acc[3]);
        acc[4] = ffma2(p2.x, w2, acc[4]);
        acc[5] = ffma2(p2.y, w2, acc[5]);
        acc[6] = ffma2(p3.x, w2, acc[6]);
        acc[7] = ffma2(p3.y, w2, acc[7]);
    }
}

// (row r, hidden j) LSTM cell update. h element (k=j, r) lives at
// (j>>1)*HSTR + r*2 + (j&1).
__device__ __forceinline__ void lstm_update(const float* __restrict__ gsh,
                                            float* __restrict__ hT,
                                            float& c, int r, int j) {
    float gi = sigmoidf_(gsh[r * GG + j]);
    float gf = sigmoidf_(gsh[r * GG + HH + j]);
    float gg = tanhf_  (gsh[r * GG + 2 * HH + j]);
    float go = sigmoidf_(gsh[r * GG + 3 * HH + j]);
    c = fmaf(gf, c, gi * gg);
    hT[(j >> 1) * HSTR + r * 2 + (j & 1)] = go * tanhf_(c);
}

__global__ void __launch_bounds__(NTH, 1)
lstm_net_kernel(const float* __restrict__ x,
                const float* __restrict__ Wih0, const float* __restrict__ Whh0,
                const float* __restrict__ bih0, const float* __restrict__ bhh0,
                const float* __restrict__ Wih1, const float* __restrict__ Whh1,
                const float* __restrict__ bih1, const float* __restrict__ bhh1,
                const float* __restrict__ Wfc1, const float* __restrict__ bfc1,
                const float* __restrict__ Wfc2, const float* __restrict__ bfc2,
                float* __restrict__ out) {
    extern __shared__ float s[];
    float* Whh0s = s + OFF_W2HH0;
    float* Wih1s = s + OFF_W2IH1;
    float* Whh1s = s + OFF_W2HH1;
    float* Wih0s = s + OFF_W2IH0;
    float* b0s   = s + OFF_B0;
    float* b1s   = s + OFF_B1;
    float* gsh   = s + OFF_GSH;
    float* hT0   = s + OFF_HT0;
    float* hT1   = s + OFF_HT1;
    float* xT    = s + OFF_XT;

    const int tid = threadIdx.x;
    const int b0  = blockIdx.x * RR;

    // ---- Load weights to shared as k-pair f32x2: W2[(kp*GG+g)*2+par] = W[g][2kp+par]
    for (int i = tid; i < HH * GG; i += NTH) {
        int g = i >> 6;
        int k = i & 63;
        int dst = ((k >> 1) * GG + g) * 2 + (k & 1);
        Whh0s[dst] = Whh0[i];
        Wih1s[dst] = Wih1[i];
        Whh1s[dst] = Whh1[i];
    }
    for (int i = tid; i < IN * GG; i += NTH) {
        int g = i / IN;
        int k = i - g * IN;
        Wih0s[((k >> 1) * GG + g) * 2 + (k & 1)] = Wih0[i];
    }
    if (tid < GG) {
        b0s[tid] = bih0[tid] + bhh0[tid];
        b1s[tid] = bih1[tid] + bhh1[tid];
    }
    for (int i = tid; i < NKP * HSTR; i += NTH) { hT0[i] = 0.0f; hT1[i] = 0.0f; }

    // x prefetch: threads 0..47 own (k, r)
    const int xk = tid >> 3;       // 0..5 (tid<48)
    const int xr = tid & 7;
    float xreg = 0.0f;
    if (tid < IN * RR)
        xreg = x[(size_t)(b0 + xr) * TT * IN + xk];

    // cell-state registers: thread owns (ur, uj) and (ur+4, uj) per layer
    const int ur = tid >> 6;       // 0..3
    const int uj = tid & 63;
    float c0a = 0.0f, c0b = 0.0f, c1a = 0.0f, c1b = 0.0f;

    __syncthreads();

    const float bias0 = b0s[tid];
    const float bias1 = b1s[tid];

    for (int t = 0; t < TT; t++) {
        // publish x_t, then prefetch x_{t+1}
        if (tid < IN * RR) xT[(xk >> 1) * HSTR + xr * 2 + (xk & 1)] = xreg;
        __syncthreads();
        if (tid < IN * RR && t + 1 < TT)
            xreg = x[(size_t)(b0 + xr) * TT * IN + (size_t)(t + 1) * IN + xk];

        // ---- Layer 0 gates: thread g computes gate g for 8 rows ----
        u64 acc[RR];
#pragma unroll
        for (int r = 0; r < RR; r++) acc[r] = 0ULL;
        mv2<NKPX>(Wih0s, xT, tid, acc);
        mv2<NKP >(Whh0s, hT0, tid, acc);
#pragma unroll
        for (int r = 0; r < RR; r++) gsh[r * GG + tid] = hsum2(acc[r]) + bias0;
        __syncthreads();

        // ---- Layer 0 cell update ----
        lstm_update(gsh, hT0, c0a, ur, uj);
        lstm_update(gsh, hT0, c0b, ur + 4, uj);
        __syncthreads();

        // ---- Layer 1 gates ----
#pragma unroll
        for (int r = 0; r < RR; r++) acc[r] = 0ULL;
        mv2<NKP>(Wih1s, hT0, tid, acc);
        mv2<NKP>(Whh1s, hT1, tid, acc);
#pragma unroll
        for (int r = 0; r < RR; r++) gsh[r * GG + tid] = hsum2(acc[r]) + bias1;
        __syncthreads();

        // ---- Layer 1 cell update ----
        lstm_update(gsh, hT1, c1a, ur, uj);
        lstm_update(gsh, hT1, c1b, ur + 4, uj);
        __syncthreads();
    }

    // ---- FC head on final h of layer 1 ----
    {
        const int wrp = tid >> 5;    // row
        const int m   = tid & 31;    // fc1 unit
        float acc2 = bfc1[m];
#pragma unroll 8
        for (int k = 0; k < HH; k++)
            acc2 = fmaf(hT1[(k >> 1) * HSTR + wrp * 2 + (k & 1)],
                        Wfc1[m * HH + k], acc2);
        acc2 = fmaxf(acc2, 0.0f) * Wfc2[m];
#pragma unroll
        for (int off = 16; off > 0; off >>= 1)
            acc2 += __shfl_down_sync(0xffffffffu, acc2, off);
        if (m == 0)
            out[b0 + wrp] = acc2 + bfc2[0];
    }
}

extern "C" void kernel_launch(void* const* d_in, const int* in_sizes, int n_in,
                              void* d_out, int out_size) {
    const float* x    = (const float*)d_in[0];
    const float* Wih0 = (const float*)d_in[1];
    const float* Whh0 = (const float*)d_in[2];
    const float* bih0 = (const float*)d_in[3];
    const float* bhh0 = (const float*)d_in[4];
    const float* Wih1 = (const float*)d_in[5];
    const float* Whh1 = (const float*)d_in[6];
    const float* bih1 = (const float*)d_in[7];
    const float* bhh1 = (const float*)d_in[8];
    const float* Wfc1 = (const float*)d_in[9];
    const float* bfc1 = (const float*)d_in[10];
    const float* Wfc2 = (const float*)d_in[11];
    const float* bfc2 = (const float*)d_in[12];
    float* out = (float*)d_out;

    cudaFuncSetAttribute(lstm_net_kernel,
                         cudaFuncAttributeMaxDynamicSharedMemorySize, SMEM_BYTES);
    lstm_net_kernel<<<NCTA, NTH, SMEM_BYTES>>>(
        x, Wih0, Whh0, bih0, bhh0, Wih1, Whh1, bih1, bhh1,
        Wfc1, bfc1, Wfc2, bfc2, out);
}

// round 3
// speedup vs baseline: 1.1743x; 1.0400x over previous
#include <cuda_runtime.h>

// Problem constants
#define BB   1024
#define TT   512
#define IN   6
#define HH   64
#define GG   256    // 4*H gate columns
#define RR   8      // batch rows per CTA
#define NTH  512    // 256 gates x 2 k-halves
#define NCTA (BB / RR)   // 128

#define NKP   (HH / 2)   // 32 k-pairs per H=64 matvec
#define NKPP  (HH / 4)   // 16 k-quads
#define NKPX  (IN / 2)   // 3 k-pairs for input dim 6
#define HSTR  20         // floats per k-pair row in hT (16 data + 4 pad)

// Shared memory layout (floats).
// W4[(kpp*GG + g)*4 + q] = W[g][4*kpp + q]   (LDS.128 per k-quad)
#define OFF_W4HH0 0                          // 16*256*4 = 16384
#define OFF_W4IH1 (OFF_W4HH0 + NKPP*GG*4)    // 16384
#define OFF_W4HH1 (OFF_W4IH1 + NKPP*GG*4)    // 16384
#define OFF_W2IH0 (OFF_W4HH1 + NKPP*GG*4)    // 3*256*2 = 1536
#define OFF_B0    (OFF_W2IH0 + NKPX*GG*2)    // 256
#define OFF_B1    (OFF_B0 + GG)              // 256
#define OFF_GSHA  (OFF_B1 + GG)              // 8*256 = 2048
#define OFF_GSHB  (OFF_GSHA + RR*GG)         // 2048
#define OFF_HT0   (OFF_GSHB + RR*GG)         // 32*20 = 640
#define OFF_HT1   (OFF_HT0 + NKP*HSTR)       // 640
#define OFF_XT    (OFF_HT1 + NKP*HSTR)       // 3*20 -> pad 64
#define SMEM_FLOATS (OFF_XT + 64)
#define SMEM_BYTES  (SMEM_FLOATS * 4)        // 226560 B

typedef unsigned long long u64;

__device__ __forceinline__ u64 ffma2(u64 a, u64 b, u64 c) {
    u64 d;
    asm("fma.rn.f32x2 %0, %1, %2, %3;" : "=l"(d) : "l"(a), "l"(b), "l"(c));
    return d;
}
__device__ __forceinline__ float hsum2(u64 a) {
    union { u64 u; float2 f; } cvt; cvt.u = a;
    return cvt.f.x + cvt.f.y;
}
__device__ __forceinline__ float fex2(float x) {
    float y; asm("ex2.approx.ftz.f32 %0, %1;" : "=f"(y) : "f"(x)); return y;
}
__device__ __forceinline__ float frcp(float x) {
    float y; asm("rcp.approx.ftz.f32 %0, %1;" : "=f"(y) : "f"(x)); return y;
}
__device__ __forceinline__ float sigmoidf_(float x) {
    return frcp(1.0f + fex2(-1.4426950408889634f * x));
}
__device__ __forceinline__ float tanhf_(float x) {
    return fmaf(2.0f, frcp(1.0f + fex2(-2.8853900817779268f * x)), -1.0f);
}

// acc[r] += over k-quads [KB, KE): W4[kpp][g] (*) h2[2kpp..2kpp+1][r]
template <int KB, int KE>
__device__ __forceinline__ void mv4(const float* __restrict__ W4s,
                                    const float* __restrict__ hT,
                                    int g, u64 acc[RR]) {
#pragma unroll
    for (int kpp = KB; kpp < KE; kpp++) {
        ulonglong2 w = *(const ulonglong2*)(W4s + (kpp * GG + g) * 4); // LDS.128
        const ulonglong2* h0 = (const ulonglong2*)(hT + (2 * kpp) * HSTR);
        const ulonglong2* h1 = (const ulonglong2*)(hT + (2 * kpp + 1) * HSTR);
        ulonglong2 a0 = h0[0], a1 = h0[1], a2 = h0[2], a3 = h0[3];
        acc[0] = ffma2(a0.x, w.x, acc[0]);
        acc[1] = ffma2(a0.y, w.x, acc[1]);
        acc[2] = ffma2(a1.x, w.x, acc[2]);
        acc[3] = ffma2(a1.y, w.x, acc[3]);
        acc[4] = ffma2(a2.x, w.x, acc[4]);
        acc[5] = ffma2(a2.y, w.x, acc[5]);
        acc[6] = ffma2(a3.x, w.x, acc[6]);
        acc[7] = ffma2(a3.y, w.x, acc[7]);
        ulonglong2 b0 = h1[0], b1 = h1[1], b2 = h1[2], b3 = h1[3];
        acc[0] = ffma2(b0.x, w.y, acc[0]);
        acc[1] = ffma2(b0.y, w.y, acc[1]);
        acc[2] = ffma2(b1.x, w.y, acc[2]);
        acc[3] = ffma2(b1.y, w.y, acc[3]);
        acc[4] = ffma2(b2.x, w.y, acc[4]);
        acc[5] = ffma2(b2.y, w.y, acc[5]);
        acc[6] = ffma2(b3.x, w.y, acc[6]);
        acc[7] = ffma2(b3.y, w.y, acc[7]);
    }
}

// x part: 3 k-pairs, f32x2 layout
__device__ __forceinline__ void mvx(const float* __restrict__ W2s,
                                    const float* __restrict__ xT,
                                    int g, u64 acc[RR]) {
#pragma unroll
    for (int kp = 0; kp < NKPX; kp++) {
        u64 w2 = *(const u64*)(W2s + (kp * GG + g) * 2);
        const ulonglong2* hp = (const ulonglong2*)(xT + kp * HSTR);
        ulonglong2 p0 = hp[0], p1 = hp[1], p2 = hp[2], p3 = hp[3];
        acc[0] = ffma2(p0.x, w2, acc[0]);
        acc[1] = ffma2(p0.y, w2, acc[1]);
        acc[2] = ffma2(p1.x, w2, acc[2]);
        acc[3] = ffma2(p1.y, w2, acc[3]);
        acc[4] = ffma2(p2.x, w2, acc[4]);
        acc[5] = ffma2(p2.y, w2, acc[5]);
        acc[6] = ffma2(p3.x, w2, acc[6]);
        acc[7] = ffma2(p3.y, w2, acc[7]);
    }
}

// (row r, hidden j) update; gates = gshA + gshB.
__device__ __forceinline__ void lstm_update(const float* __restrict__ gA,
                                            const float* __restrict__ gB,
                                            float* __restrict__ hT,
                                            float& c, int r, int j) {
    int idx = r * GG + j;
    float gi = sigmoidf_(gA[idx] + gB[idx]);
    float gf = sigmoidf_(gA[idx + HH] + gB[idx + HH]);
    float gg = tanhf_  (gA[idx + 2 * HH] + gB[idx + 2 * HH]);
    float go = sigmoidf_(gA[idx + 3 * HH] + gB[idx + 3 * HH]);
    c = fmaf(gf, c, gi * gg);
    hT[(j >> 1) * HSTR + r * 2 + (j & 1)] = go * tanhf_(c);
}

__global__ void __launch_bounds__(NTH, 1)
lstm_net_kernel(const float* __restrict__ x,
                const float* __restrict__ Wih0, const float* __restrict__ Whh0,
                const float* __restrict__ bih0, const float* __restrict__ bhh0,
                const float* __restrict__ Wih1, const float* __restrict__ Whh1,
                const float* __restrict__ bih1, const float* __restrict__ bhh1,
                const float* __restrict__ Wfc1, const float* __restrict__ bfc1,
                const float* __restrict__ Wfc2, const float* __restrict__ bfc2,
                float* __restrict__ out) {
    extern __shared__ float s[];
    float* Whh0s = s + OFF_W4HH0;
    float* Wih1s = s + OFF_W4IH1;
    float* Whh1s = s + OFF_W4HH1;
    float* Wih0s = s + OFF_W2IH0;
    float* b0s   = s + OFF_B0;
    float* b1s   = s + OFF_B1;
    float* gshA  = s + OFF_GSHA;
    float* gshB  = s + OFF_GSHB;
    float* hT0   = s + OFF_HT0;
    float* hT1   = s + OFF_HT1;
    float* xT    = s + OFF_XT;

    const int tid  = threadIdx.x;
    const int g    = tid & 255;
    const int half = tid >> 8;
    const int b0   = blockIdx.x * RR;

    // ---- Weights -> shared, k-quad layout: W4[(kpp*GG+g)*4 + (k&3)]
    for (int i = tid; i < HH * GG; i += NTH) {
        int gg_ = i >> 6;
        int k   = i & 63;
        int dst = ((k >> 2) * GG + gg_) * 4 + (k & 3);
        Whh0s[dst] = Whh0[i];
        Wih1s[dst] = Wih1[i];
        Whh1s[dst] = Whh1[i];
    }
    for (int i = tid; i < IN * GG; i += NTH) {
        int gg_ = i / IN;
        int k   = i - gg_ * IN;
        Wih0s[((k >> 1) * GG + gg_) * 2 + (k & 1)] = Wih0[i];
    }
    if (tid < GG) {
        b0s[tid] = bih0[tid] + bhh0[tid];
        b1s[tid] = bih1[tid] + bhh1[tid];
    }
    for (int i = tid; i < NKP * HSTR; i += NTH) { hT0[i] = 0.0f; hT1[i] = 0.0f; }

    // x prefetch: threads 0..47 own (k, r)
    const int xk = tid >> 3;
    const int xr = tid & 7;
    float xreg = 0.0f;
    if (tid < IN * RR)
        xreg = x[(size_t)(b0 + xr) * TT * IN + xk];

    // update mapping: this thread owns (ur, uj), one cell per layer
    const int ur = tid >> 6;      // 0..7
    const int uj = tid & 63;
    float c0 = 0.0f, c1 = 0.0f;

    __syncthreads();

    const float bias0 = b0s[g];
    const float bias1 = b1s[g];

    // publish x_0
    if (tid < IN * RR) xT[(xk >> 1) * HSTR + xr * 2 + (xk & 1)] = xreg;
    __syncthreads();

    for (int t = 0; t < TT; t++) {
        // prefetch x_{t+1}
        if (tid < IN * RR && t + 1 < TT)
            xreg = x[(size_t)(b0 + xr) * TT * IN + (size_t)(t + 1) * IN + xk];

        // ---- Layer 0 gates (k-split halves) ----
        u64 acc[RR];
#pragma unroll
        for (int r = 0; r < RR; r++) acc[r] = 0ULL;
        if (half == 0) {
            mvx(Wih0s, xT, g, acc);
            mv4<0, NKPP / 2>(Whh0s, hT0, g, acc);
#pragma unroll
            for (int r = 0; r < RR; r++) gshA[r * GG + g] = hsum2(acc[r]) + bias0;
        } else {
            mv4<NKPP / 2, NKPP>(Whh0s, hT0, g, acc);
#pragma unroll
            for (int r = 0; r < RR; r++) gshB[r * GG + g] = hsum2(acc[r]);
        }
        __syncthreads();

        // ---- Layer 0 update ----
        lstm_update(gshA, gshB, hT0, c0, ur, uj);
        __syncthreads();

        // ---- Layer 1 gates ----
#pragma unroll
        for (int r = 0; r < RR; r++) acc[r] = 0ULL;
        if (half == 0) {
            mv4<0, NKPP / 2>(Wih1s, hT0, g, acc);
            mv4<0, NKPP / 2>(Whh1s, hT1, g, acc);
#pragma unroll
            for (int r = 0; r < RR; r++) gshA[r * GG + g] = hsum2(acc[r]) + bias1;
        } else {
            mv4<NKPP / 2, NKPP>(Wih1s, hT0, g, acc);
            mv4<NKPP / 2, NKPP>(Whh1s, hT1, g, acc);
#pragma unroll
            for (int r = 0; r < RR; r++) gshB[r * GG + g] = hsum2(acc[r]);
        }
        __syncthreads();

        // ---- Layer 1 update + publish x_{t+1} ----
        lstm_update(gshA, gshB, hT1, c1, ur, uj);
        if (tid < IN * RR && t + 1 < TT)
            xT[(xk >> 1) * HSTR + xr * 2 + (xk & 1)] = xreg;
        __syncthreads();
    }

    // ---- FC head on final h of layer 1 (first 256 threads) ----
    if (tid < 256) {
        const int wrp = tid >> 5;    // row
        const int m   = tid & 31;    // fc1 unit
        float acc2 = bfc1[m];
#pragma unroll 8
        for (int k = 0; k < HH; k++)
            acc2 = fmaf(hT1[(k >> 1) * HSTR + wrp * 2 + (k & 1)],
                        Wfc1[m * HH + k], acc2);
        acc2 = fmaxf(acc2, 0.0f) * Wfc2[m];
#pragma unroll
        for (int off = 16; off > 0; off >>= 1)
            acc2 += __shfl_down_sync(0xffffffffu, acc2, off);
        if (m == 0)
            out[b0 + wrp] = acc2 + bfc2[0];
    }
}

extern "C" void kernel_launch(void* const* d_in, const int* in_sizes, int n_in,
                              void* d_out, int out_size) {
    const float* x    = (const float*)d_in[0];
    const float* Wih0 = (const float*)d_in[1];
    const float* Whh0 = (const float*)d_in[2];
    const float* bih0 = (const float*)d_in[3];
    const float* bhh0 = (const float*)d_in[4];
    const float* Wih1 = (const float*)d_in[5];
    const float* Whh1 = (const float*)d_in[6];
    const float* bih1 = (const float*)d_in[7];
    const float* bhh1 = (const float*)d_in[8];
    const float* Wfc1 = (const float*)d_in[9];
    const float* bfc1 = (const float*)d_in[10];
    const float* Wfc2 = (const float*)d_in[11];
    const float* bfc2 = (const float*)d_in[12];
    float* out = (float*)d_out;

    cudaFuncSetAttribute(lstm_net_kernel,
                         cudaFuncAttributeMaxDynamicSharedMemorySize, SMEM_BYTES);
    lstm_net_kernel<<<NCTA, NTH, SMEM_BYTES>>>(
        x, Wih0, Whh0, bih0, bhh0, Wih1, Whh1, bih1, bhh1,
        Wfc1, bfc1, Wfc2, bfc2, out);
}

// round 4
// speedup vs baseline: 1.4295x; 1.2173x over previous
#include <cuda_runtime.h>

#define BB   1024
#define TT   512
#define IN   6
#define HH   64
#define GG   256
#define RR   8
#define NTH  512
#define NCTA (BB / RR)

#define NKQ   16     // k-quads per H matvec
#define HSTRF 20     // floats per kp row (16 data + 4 pad)
#define HGAP  16     // extra gap before kp 16 (banks: 16*80+64 = 1344 % 128 = 64)

// smem offsets (floats)
#define OFF_W4HH0 0
#define OFF_W4IH1 (OFF_W4HH0 + NKQ*GG*4)   // 16384
#define OFF_W4HH1 (OFF_W4IH1 + NKQ*GG*4)   // 32768
#define OFF_W2IH0 (OFF_W4HH1 + NKQ*GG*4)   // 49152 (3 kp * 256 * 2 = 1536)
#define OFF_B0    (OFF_W2IH0 + 1536)
#define OFF_B1    (OFF_B0 + GG)
#define OFF_GSH1  (OFF_B1 + GG)            // [g][r] 2048
#define OFF_GSHP  (OFF_GSH1 + GG*RR)       // 2048
#define OFF_HT0   (OFF_GSHP + GG*RR)       // 656
#define OFF_HT1   (OFF_HT0 + 656)
#define OFF_XT    (OFF_HT1 + 656)          // 3*16 + pad
#define SMEM_FLOATS (OFF_XT + 64)
#define SMEM_BYTES  (SMEM_FLOATS * 4)      // 226688 B

typedef unsigned long long u64;

__device__ __forceinline__ u64 ffma2(u64 a, u64 b, u64 c) {
    u64 d;
    asm("fma.rn.f32x2 %0, %1, %2, %3;" : "=l"(d) : "l"(a), "l"(b), "l"(c));
    return d;
}
__device__ __forceinline__ float hsum2(u64 a) {
    union { u64 u; float2 f; } cvt; cvt.u = a;
    return cvt.f.x + cvt.f.y;
}
__device__ __forceinline__ float fex2(float x) {
    float y; asm("ex2.approx.ftz.f32 %0, %1;" : "=f"(y) : "f"(x)); return y;
}
__device__ __forceinline__ float frcp(float x) {
    float y; asm("rcp.approx.ftz.f32 %0, %1;" : "=f"(y) : "f"(x)); return y;
}
__device__ __forceinline__ float sigmoidf_(float x) {
    return frcp(1.0f + fex2(-1.4426950408889634f * x));
}
__device__ __forceinline__ float tanhf_(float x) {
    return fmaf(2.0f, frcp(1.0f + fex2(-2.8853900817779268f * x)), -1.0f);
}
__device__ __forceinline__ int hoff(int kp) {
    return kp * HSTRF + (kp >= 16 ? HGAP : 0);
}

__global__ void __launch_bounds__(NTH, 1)
lstm_net_kernel(const float* __restrict__ x,
                const float* __restrict__ Wih0, const float* __restrict__ Whh0,
                const float* __restrict__ bih0, const float* __restrict__ bhh0,
                const float* __restrict__ Wih1, const float* __restrict__ Whh1,
                const float* __restrict__ bih1, const float* __restrict__ bhh1,
                const float* __restrict__ Wfc1, const float* __restrict__ bfc1,
                const float* __restrict__ Wfc2, const float* __restrict__ bfc2,
                float* __restrict__ out) {
    extern __shared__ float s[];
    float* Whh0s = s + OFF_W4HH0;
    float* Wih1s = s + OFF_W4IH1;
    float* Whh1s = s + OFF_W4HH1;
    float* Wih0s = s + OFF_W2IH0;
    float* b0s   = s + OFF_B0;
    float* b1s   = s + OFF_B1;
    float* gsh1  = s + OFF_GSH1;   // layer-1 gates (t)     [g][r]
    float* gshP  = s + OFF_GSHP;   // layer-0 gates (t+1)   [g][r]
    float* hT0   = s + OFF_HT0;
    float* hT1   = s + OFF_HT1;
    float* xT    = s + OFF_XT;

    const int tid  = threadIdx.x;
    const int lane = tid & 31;
    const int wrp  = tid >> 5;
    const int g    = wrp * 16 + (lane & 15);   // gate column
    const int half = lane >> 4;                // k-half (0: kq 0..7, 1: kq 8..15)
    const int b0   = blockIdx.x * RR;

    // ---- Stage weights: quad layout W4[(kq*GG+g)*4 + (k&3)]
    for (int i = tid; i < HH * GG; i += NTH) {
        int gg_ = i >> 6;
        int k   = i & 63;
        int dst = ((k >> 2) * GG + gg_) * 4 + (k & 3);
        Whh0s[dst] = Whh0[i];
        Wih1s[dst] = Wih1[i];
        Whh1s[dst] = Whh1[i];
    }
    for (int i = tid; i < IN * GG; i += NTH) {
        int gg_ = i / IN;
        int k   = i - gg_ * IN;
        Wih0s[((k >> 1) * GG + gg_) * 2 + (k & 1)] = Wih0[i];
    }
    if (tid < GG) {
        b0s[tid] = bih0[tid] + bhh0[tid];
        b1s[tid] = bih1[tid] + bhh1[tid];
    }
    for (int i = tid; i < 656; i += NTH) { hT0[i] = 0.0f; hT1[i] = 0.0f; }

    // x staging threads
    const int xk = tid >> 3;       // 0..5 for tid<48
    const int xr = tid & 7;
    float xreg = 0.0f;
    if (tid < IN * RR) xreg = x[(size_t)(b0 + xr) * TT * IN + xk];   // x_0

    // update role: (r = tid&7, j = tid>>3)
    const int ur = tid & 7;
    const int uj = tid >> 3;
    float c0 = 0.0f, c1 = 0.0f;

    __syncthreads();

    const float bias0 = b0s[g];
    const float bias1 = b1s[g];
    const int kqb = half * 8;

    // publish x_0
    if (tid < IN * RR) xT[(xk >> 1) * 16 + xr * 2 + (xk & 1)] = xreg;
    __syncthreads();

    // ================= PROLOGUE: gates0_0 = bias0 + Wih0 @ x_0 =================
    {
        u64 accP[RR];
#pragma unroll
        for (int r = 0; r < RR; r++) accP[r] = 0ULL;
        if (half == 1) {
#pragma unroll
            for (int kp = 0; kp < 3; kp++) {
                u64 w2 = *(const u64*)(Wih0s + (kp * GG + g) * 2);
                const ulonglong2* hp = (const ulonglong2*)(xT + kp * 16);
                ulonglong2 p0 = hp[0], p1 = hp[1], p2 = hp[2], p3 = hp[3];
                accP[0] = ffma2(p0.x, w2, accP[0]);
                accP[1] = ffma2(p0.y, w2, accP[1]);
                accP[2] = ffma2(p1.x, w2, accP[2]);
                accP[3] = ffma2(p1.y, w2, accP[3]);
                accP[4] = ffma2(p2.x, w2, accP[4]);
                accP[5] = ffma2(p2.y, w2, accP[5]);
                accP[6] = ffma2(p3.x, w2, accP[6]);
                accP[7] = ffma2(p3.y, w2, accP[7]);
            }
        }
        float sP[RR];
#pragma unroll
        for (int r = 0; r < RR; r++) sP[r] = hsum2(accP[r]);
#pragma unroll
        for (int r = 0; r < RR; r++)
            sP[r] += __shfl_down_sync(0xffffffffu, sP[r], 16);
        if (half == 0) {
            float4 v0 = make_float4(sP[0] + bias0, sP[1] + bias0, sP[2] + bias0, sP[3] + bias0);
            float4 v1 = make_float4(sP[4] + bias0, sP[5] + bias0, sP[6] + bias0, sP[7] + bias0);
            *(float4*)(gshP + g * 8)     = v0;
            *(float4*)(gshP + g * 8 + 4) = v1;
        }
        if (tid < IN * RR)   // load x_1
            xreg = x[(size_t)(b0 + xr) * TT * IN + 1 * IN + xk];
        __syncthreads();

        // prologue update: layer 0 only -> h0_0
        float gi = sigmoidf_(gshP[uj * 8 + ur]);
        float gf = sigmoidf_(gshP[(uj + 64) * 8 + ur]);
        float gc = tanhf_  (gshP[(uj + 128) * 8 + ur]);
        float go = sigmoidf_(gshP[(uj + 192) * 8 + ur]);
        c0 = fmaf(gf, c0, gi * gc);
        hT0[hoff(uj >> 1) + ur * 2 + (uj & 1)] = go * tanhf_(c0);
        if (tid < IN * RR) xT[(xk >> 1) * 16 + xr * 2 + (xk & 1)] = xreg;  // publish x_1
        __syncthreads();
    }

    // ================= MAIN LOOP =================
    for (int t = 0; t < TT; t++) {
        // ---------- PHASE 1: gate math ----------
        // acc1 = Wih1@h0_t + Whh1@h1_{t-1}    (layer-1 gates, step t)
        // accP = Whh0@h0_t + Wih0@x_{t+1}     (layer-0 gates, step t+1)
        u64 acc1[RR], accP[RR];
#pragma unroll
        for (int r = 0; r < RR; r++) { acc1[r] = 0ULL; accP[r] = 0ULL; }

        // fused h0 loop (two weight streams, one h stream)
#pragma unroll
        for (int i = 0; i < 8; i++) {
            int kq = kqb + i;
            ulonglong2 w1 = *(const ulonglong2*)(Wih1s + (kq * GG + g) * 4);
            ulonglong2 wp = *(const ulonglong2*)(Whh0s + (kq * GG + g) * 4);
            const ulonglong2* ha = (const ulonglong2*)(hT0 + hoff(2 * kq));
            const ulonglong2* hb = (const ulonglong2*)(hT0 + hoff(2 * kq + 1));
#pragma unroll
            for (int c = 0; c < 4; c++) {
                ulonglong2 hv = ha[c];
                acc1[2*c]   = ffma2(hv.x, w1.x, acc1[2*c]);
                accP[2*c]   = ffma2(hv.x, wp.x, accP[2*c]);
                acc1[2*c+1] = ffma2(hv.y, w1.x, acc1[2*c+1]);
                accP[2*c+1] = ffma2(hv.y, wp.x, accP[2*c+1]);
            }
#pragma unroll
            for (int c = 0; c < 4; c++) {
                ulonglong2 hv = hb[c];
                acc1[2*c]   = ffma2(hv.x, w1.y, acc1[2*c]);
                accP[2*c]   = ffma2(hv.x, wp.y, accP[2*c]);
                acc1[2*c+1] = ffma2(hv.y, w1.y, acc1[2*c+1]);
                accP[2*c+1] = ffma2(hv.y, wp.y, accP[2*c+1]);
            }
        }
        // h1 loop
#pragma unroll
        for (int i = 0; i < 8; i++) {
            int kq = kqb + i;
            ulonglong2 w1 = *(const ulonglong2*)(Whh1s + (kq * GG + g) * 4);
            const ulonglong2* ha = (const ulonglong2*)(hT1 + hoff(2 * kq));
            const ulonglong2* hb = (const ulonglong2*)(hT1 + hoff(2 * kq + 1));
#pragma unroll
            for (int c = 0; c < 4; c++) {
                ulonglong2 hv = ha[c];
                acc1[2*c]   = ffma2(hv.x, w1.x, acc1[2*c]);
                acc1[2*c+1] = ffma2(hv.y, w1.x, acc1[2*c+1]);
            }
#pragma unroll
            for (int c = 0; c < 4; c++) {
                ulonglong2 hv = hb[c];
                acc1[2*c]   = ffma2(hv.x, w1.y, acc1[2*c]);
                acc1[2*c+1] = ffma2(hv.y, w1.y, acc1[2*c+1]);
            }
        }
        // x part (half 1): accP += Wih0 @ x_{t+1}  (xT holds x_{t+1})
        if (half == 1) {
#pragma unroll
            for (int kp = 0; kp < 3; kp++) {
                u64 w2 = *(const u64*)(Wih0s + (kp * GG + g) * 2);
                const ulonglong2* hp = (const ulonglong2*)(xT + kp * 16);
                ulonglong2 p0 = hp[0], p1 = hp[1], p2 = hp[2], p3 = hp[3];
                accP[0] = ffma2(p0.x, w2, accP[0]);
                accP[1] = ffma2(p0.y, w2, accP[1]);
                accP[2] = ffma2(p1.x, w2, accP[2]);
                accP[3] = ffma2(p1.y, w2, accP[3]);
                accP[4] = ffma2(p2.x, w2, accP[4]);
                accP[5] = ffma2(p2.y, w2, accP[5]);
                accP[6] = ffma2(p3.x, w2, accP[6]);
                accP[7] = ffma2(p3.y, w2, accP[7]);
            }
        }
        // prefetch x_{t+2}
        if (tid < IN * RR && t + 2 < TT)
            xreg = x[(size_t)(b0 + xr) * TT * IN + (size_t)(t + 2) * IN + xk];

        // combine k-halves in-warp, store gates
        float s1[RR], sP[RR];
#pragma unroll
        for (int r = 0; r < RR; r++) { s1[r] = hsum2(acc1[r]); sP[r] = hsum2(accP[r]); }
#pragma unroll
        for (int r = 0; r < RR; r++) {
            s1[r] += __shfl_down_sync(0xffffffffu, s1[r], 16);
            sP[r] += __shfl_down_sync(0xffffffffu, sP[r], 16);
        }
        if (half == 0) {
            *(float4*)(gsh1 + g * 8)     = make_float4(s1[0] + bias1, s1[1] + bias1, s1[2] + bias1, s1[3] + bias1);
            *(float4*)(gsh1 + g * 8 + 4) = make_float4(s1[4] + bias1, s1[5] + bias1, s1[6] + bias1, s1[7] + bias1);
            *(float4*)(gshP + g * 8)     = make_float4(sP[0] + bias0, sP[1] + bias0, sP[2] + bias0, sP[3] + bias0);
            *(float4*)(gshP + g * 8 + 4) = make_float4(sP[4] + bias0, sP[5] + bias0, sP[6] + bias0, sP[7] + bias0);
        }
        __syncthreads();

        // ---------- PHASE 2: both cell updates ----------
        {
            float gi = sigmoidf_(gsh1[uj * 8 + ur]);
            float gf = sigmoidf_(gsh1[(uj + 64) * 8 + ur]);
            float gc = tanhf_  (gsh1[(uj + 128) * 8 + ur]);
            float go = sigmoidf_(gsh1[(uj + 192) * 8 + ur]);
            c1 = fmaf(gf, c1, gi * gc);
            hT1[hoff(uj >> 1) + ur * 2 + (uj & 1)] = go * tanhf_(c1);   // h1_t
        }
        {
            float gi = sigmoidf_(gshP[uj * 8 + ur]);
            float gf = sigmoidf_(gshP[(uj + 64) * 8 + ur]);
            float gc = tanhf_  (gshP[(uj + 128) * 8 + ur]);
            float go = sigmoidf_(gshP[(uj + 192) * 8 + ur]);
            c0 = fmaf(gf, c0, gi * gc);
            hT0[hoff(uj >> 1) + ur * 2 + (uj & 1)] = go * tanhf_(c0);   // h0_{t+1}
        }
        if (tid < IN * RR && t + 2 < TT)
            xT[(xk >> 1) * 16 + xr * 2 + (xk & 1)] = xreg;              // publish x_{t+2}
        __syncthreads();
    }

    // ================= FC head on h1_{T-1} =================
    if (tid < 256) {
        const int row = tid >> 5;
        const int m   = tid & 31;
        float acc2 = bfc1[m];
#pragma unroll 8
        for (int k = 0; k < HH; k++)
            acc2 = fmaf(hT1[hoff(k >> 1) + row * 2 + (k & 1)],
                        Wfc1[m * HH + k], acc2);
        acc2 = fmaxf(acc2, 0.0f) * Wfc2[m];
#pragma unroll
        for (int off = 16; off > 0; off >>= 1)
            acc2 += __shfl_down_sync(0xffffffffu, acc2, off);
        if (m == 0)
            out[b0 + row] = acc2 + bfc2[0];
    }
}

extern "C" void kernel_launch(void* const* d_in, const int* in_sizes, int n_in,
                              void* d_out, int out_size) {
    const float* x    = (const float*)d_in[0];
    const float* Wih0 = (const float*)d_in[1];
    const float* Whh0 = (const float*)d_in[2];
    const float* bih0 = (const float*)d_in[3];
    const float* bhh0 = (const float*)d_in[4];
    const float* Wih1 = (const float*)d_in[5];
    const float* Whh1 = (const float*)d_in[6];
    const float* bih1 = (const float*)d_in[7];
    const float* bhh1 = (const float*)d_in[8];
    const float* Wfc1 = (const float*)d_in[9];
    const float* bfc1 = (const float*)d_in[10];
    const float* Wfc2 = (const float*)d_in[11];
    const float* bfc2 = (const float*)d_in[12];
    float* out = (float*)d_out;

    cudaFuncSetAttribute(lstm_net_kernel,
                         cudaFuncAttributeMaxDynamicSharedMemorySize, SMEM_BYTES);
    lstm_net_kernel<<<NCTA, NTH, SMEM_BYTES>>>(
        x, Wih0, Whh0, bih0, bhh0, Wih1, Whh1, bih1, bhh1,
        Wfc1, bfc1, Wfc2, bfc2, out);
}